// round 8
// baseline (speedup 1.0000x reference)
#include <cuda_runtime.h>
#include <cuda_fp16.h>
#include <cstdint>

#define THREADS 256
#define TPC     4        // tiles per CTA
#define TILE    128
#define XS_H    120      // halves; 240B row, 240/16=15 ≡ 7 mod 8 -> ldmatrix conflict-free
#define W1_H    120
#define HS_H    72       // 144B row, 9 ≡ 1 mod 8 -> ldmatrix conflict-free

// smem (halves): xs 128*120=15360 (h [128][72] aliases), w1 64*120=7680; fp32 b1 64, b2 32
#define SM_BYTES ((128 * XS_H + 64 * W1_H) * 2 + (64 + 32) * 4)

__device__ __forceinline__ uint2 f4_to_h4(float4 v) {
    __half2 lo = __floats2half2_rn(v.x, v.y);
    __half2 hi = __floats2half2_rn(v.z, v.w);
    uint2 r; r.x = *(uint32_t*)&lo; r.y = *(uint32_t*)&hi; return r;
}
__device__ __forceinline__ uint32_t f2_to_h2(float x, float y) {
    __half2 h = __floats2half2_rn(x, y);
    return *(uint32_t*)&h;
}
__device__ __forceinline__ uint32_t s2u(const void* p) {
    uint32_t a;
    asm("{ .reg .u64 t; cvta.to.shared.u64 t, %1; cvt.u32.u64 %0, t; }" : "=r"(a) : "l"(p));
    return a;
}
__device__ __forceinline__ void ldm_x4(uint32_t* r, uint32_t addr) {
    asm volatile("ldmatrix.sync.aligned.m8n8.x4.shared.b16 {%0,%1,%2,%3}, [%4];"
        : "=r"(r[0]), "=r"(r[1]), "=r"(r[2]), "=r"(r[3]) : "r"(addr));
}
__device__ __forceinline__ void mma_f16(float* d, const uint32_t* a, const uint32_t* b) {
    asm volatile(
        "mma.sync.aligned.m16n8k16.row.col.f32.f16.f16.f32 "
        "{%0,%1,%2,%3}, {%4,%5,%6,%7}, {%8,%9}, {%0,%1,%2,%3};"
        : "+f"(d[0]), "+f"(d[1]), "+f"(d[2]), "+f"(d[3])
        : "r"(a[0]), "r"(a[1]), "r"(a[2]), "r"(a[3]), "r"(b[0]), "r"(b[1]));
}

extern "C" __global__ void __launch_bounds__(THREADS, 2)
edge_mlp_lm(const float* __restrict__ src, const float* __restrict__ dst,
            const float* __restrict__ ea, const float* __restrict__ u,
            const int* __restrict__ batch,
            const float* __restrict__ W1, const float* __restrict__ b1,
            const float* __restrict__ W2, const float* __restrict__ b2,
            float* __restrict__ out, int E, int ntiles)
{
    extern __shared__ char smraw[];
    __half* xs  = (__half*)smraw;                 // [128][XS_H], aliased by h [128][HS_H]
    __half* w1s = xs + 128 * XS_H;                // [64 n][W1_H k]
    float*  b1s = (float*)(w1s + 64 * W1_H);      // 64
    float*  b2s = b1s + 64;                       // 32

    const int t    = threadIdx.x;
    const int w    = t >> 5;
    const int lane = t & 31;
    const int gid  = lane >> 2;     // 0..7
    const int ctid = lane & 3;      // 0..3
    const int mbase = (w & 3) * 32;
    const int nbase = (w >> 2) * 32;   // GEMM1 N slice (0 or 32)
    const int nb2   = (w >> 2) * 16;   // GEMM2 N slice

    // ldmatrix per-lane byte offsets
    // A/H: matrices (rows0-7,k0),(rows8-15,k0),(rows0-7,k8),(rows8-15,k8)
    const int rp   = ((lane >> 3) & 1) * 8 + (lane & 7);   // row within 16
    const int kp   = (lane >> 4) * 16;                     // 0 or 16 bytes (8 halves)
    const int aoff = rp * (XS_H * 2) + kp;
    const int hoff = rp * (HS_H * 2) + kp;
    // B: matrices (n0-7,k0),(n0-7,k8),(n8-15,k0),(n8-15,k8)
    const int np   = ((lane >> 4) & 1) * 8 + (lane & 7);
    const int bkp  = ((lane >> 3) & 1) * 16;
    const int boff = np * (W1_H * 2) + bkp;

    const uint32_t xs_u = s2u(xs);
    const uint32_t w1_u = s2u(w1s);

    // ---- stage W1 as [n][k] halves ----
    {
        const float2* w12 = (const float2*)W1;     // 64*56 float2
        #pragma unroll
        for (int it = 0; it < 14; it++) {
            int i = t + it * THREADS;
            int n = i / 56, k2 = i % 56;
            float2 v = w12[i];
            *(uint32_t*)&w1s[n * W1_H + 2 * k2] = f2_to_h2(v.x, v.y);
        }
        if (t < 64) b1s[t] = b1[t];
        if (t < 32) b2s[t] = b2[t];
    }

    // ---- W2 fragments persist in registers ----
    uint32_t w2r[4][2][2];   // [ks][nt][b0/b1]
    #pragma unroll
    for (int ks = 0; ks < 4; ks++)
        #pragma unroll
        for (int nt = 0; nt < 2; nt++) {
            int n  = nb2 + 8 * nt + gid;
            int k0 = 16 * ks + 2 * ctid;
            float2 v0 = *(const float2*)&W2[n * 64 + k0];
            float2 v1 = *(const float2*)&W2[n * 64 + k0 + 8];
            w2r[ks][nt][0] = f2_to_h2(v0.x, v0.y);
            w2r[ks][nt][1] = f2_to_h2(v1.x, v1.y);
        }

    const float4* src4 = (const float4*)src;
    const float4* dst4 = (const float4*)dst;
    const float4* ea4  = (const float4*)ea;
    const float4* u4   = (const float4*)u;

    const int oks   = nbase >> 4;          // own GEMM2 ks: oks, oks+1
    const int pbase = (nbase ^ 32) >> 4;   // partner ks base

    #pragma unroll 1
    for (int j = 0; j < TPC; j++) {
        const int tile = blockIdx.x * TPC + j;
        if (tile >= ntiles) break;
        const int e0 = tile * TILE;

        // ---- stage x tile: [128][112] halves = [src|dst|ea|u[batch]] ----
        #pragma unroll
        for (int blk = 0; blk < 3; blk++) {
            const float4* a4 = (blk == 0) ? src4 : (blk == 1) ? dst4 : ea4;
            #pragma unroll
            for (int it = 0; it < 4; it++) {
                int r = (t >> 3) + 32 * it, c = t & 7;
                int e = e0 + r;
                float4 v = make_float4(0.f, 0.f, 0.f, 0.f);
                if (e < E) v = a4[(size_t)e * 8 + c];
                *(uint2*)&xs[r * XS_H + blk * 32 + c * 4] = f4_to_h4(v);
            }
        }
        #pragma unroll
        for (int it = 0; it < 2; it++) {
            int r = (t >> 2) + 64 * it, c = t & 3;
            int e = e0 + r;
            float4 v = make_float4(0.f, 0.f, 0.f, 0.f);
            if (e < E) { int bi = batch[e]; v = u4[(size_t)bi * 4 + c]; }
            *(uint2*)&xs[r * XS_H + 96 + c * 4] = f4_to_h4(v);
        }
        __syncthreads();

        // ================= GEMM1: [128x112] @ [112x64] via ldmatrix =============
        float acc[2][4][4];
        #pragma unroll
        for (int mt = 0; mt < 2; mt++)
            #pragma unroll
            for (int nt = 0; nt < 4; nt++)
                #pragma unroll
                for (int q = 0; q < 4; q++) acc[mt][nt][q] = 0.f;

        #pragma unroll
        for (int ks = 0; ks < 7; ks++) {
            uint32_t a[2][4], b[2][4];   // b[ntp]: {b[2ntp][0],b[2ntp][1],b[2ntp+1][0],b[2ntp+1][1]}
            #pragma unroll
            for (int mt = 0; mt < 2; mt++)
                ldm_x4(a[mt], xs_u + (mbase + 16 * mt) * (XS_H * 2) + aoff + ks * 32);
            #pragma unroll
            for (int ntp = 0; ntp < 2; ntp++)
                ldm_x4(b[ntp], w1_u + (nbase + 16 * ntp) * (W1_H * 2) + boff + ks * 32);
            #pragma unroll
            for (int mt = 0; mt < 2; mt++)
                #pragma unroll
                for (int ntp = 0; ntp < 2; ntp++) {
                    mma_f16(acc[mt][2 * ntp],     a[mt], &b[ntp][0]);
                    mma_f16(acc[mt][2 * ntp + 1], a[mt], &b[ntp][2]);
                }
        }
        __syncthreads();   // all warps done reading xs before h overwrites it

        // ---- epilogue 1: bias+relu -> packed h2 kept in regs AND stored to h ----
        __half* h = xs;    // [128][HS_H]
        uint32_t hh[2][4][2];   // [mt][nt][row g / row g+8] packed pairs
        #pragma unroll
        for (int mt = 0; mt < 2; mt++) {
            int r0 = mbase + 16 * mt + gid;
            #pragma unroll
            for (int nt = 0; nt < 4; nt++) {
                int c = nbase + 8 * nt + 2 * ctid;
                float bx = b1s[c], by = b1s[c + 1];
                hh[mt][nt][0] = f2_to_h2(fmaxf(acc[mt][nt][0] + bx, 0.f),
                                         fmaxf(acc[mt][nt][1] + by, 0.f));
                hh[mt][nt][1] = f2_to_h2(fmaxf(acc[mt][nt][2] + bx, 0.f),
                                         fmaxf(acc[mt][nt][3] + by, 0.f));
                *(uint32_t*)&h[r0 * HS_H + c]       = hh[mt][nt][0];
                *(uint32_t*)&h[(r0 + 8) * HS_H + c] = hh[mt][nt][1];
            }
        }

        // ================= GEMM2: [128x64] @ [64x32] =================
        float acc2[2][2][4];
        #pragma unroll
        for (int mt = 0; mt < 2; mt++)
            #pragma unroll
            for (int nt = 0; nt < 2; nt++)
                #pragma unroll
                for (int q = 0; q < 4; q++) acc2[mt][nt][q] = 0.f;

        // own-half ks from registers (before barrier: overlaps STS drain)
        #pragma unroll
        for (int kk = 0; kk < 2; kk++) {
            #pragma unroll
            for (int mt = 0; mt < 2; mt++) {
                uint32_t a[4] = { hh[mt][2 * kk][0], hh[mt][2 * kk][1],
                                  hh[mt][2 * kk + 1][0], hh[mt][2 * kk + 1][1] };
                mma_f16(acc2[mt][0], a, w2r[oks + kk][0]);
                mma_f16(acc2[mt][1], a, w2r[oks + kk][1]);
            }
        }
        __syncthreads();   // h visible to partner warps

        // partner-half ks via ldmatrix
        #pragma unroll
        for (int kk = 0; kk < 2; kk++) {
            int pks = pbase + kk;
            #pragma unroll
            for (int mt = 0; mt < 2; mt++) {
                uint32_t a[4];
                ldm_x4(a, xs_u + (mbase + 16 * mt) * (HS_H * 2) + hoff + pks * 32);
                mma_f16(acc2[mt][0], a, w2r[pks][0]);
                mma_f16(acc2[mt][1], a, w2r[pks][1]);
            }
        }

        // ---- epilogue 2: bias + store to gmem ----
        #pragma unroll
        for (int mt = 0; mt < 2; mt++) {
            int e = e0 + mbase + 16 * mt + gid;
            #pragma unroll
            for (int nt = 0; nt < 2; nt++) {
                int c = nb2 + 8 * nt + 2 * ctid;
                float bx = b2s[c], by = b2s[c + 1];
                if (e < E) {
                    float2 v; v.x = acc2[mt][nt][0] + bx; v.y = acc2[mt][nt][1] + by;
                    *(float2*)&out[(size_t)e * 32 + c] = v;
                }
                if (e + 8 < E) {
                    float2 v; v.x = acc2[mt][nt][2] + bx; v.y = acc2[mt][nt][3] + by;
                    *(float2*)&out[(size_t)(e + 8) * 32 + c] = v;
                }
            }
        }
        __syncthreads();   // h readers done before next tile's staging overwrites xs
    }
}

extern "C" void kernel_launch(void* const* d_in, const int* in_sizes, int n_in,
                              void* d_out, int out_size) {
    const float* src   = (const float*)d_in[0];
    const float* dst   = (const float*)d_in[1];
    const float* ea    = (const float*)d_in[2];
    const float* u     = (const float*)d_in[3];
    const int*   batch = (const int*)d_in[4];
    const float* W1    = (const float*)d_in[5];
    const float* b1    = (const float*)d_in[6];
    const float* W2    = (const float*)d_in[7];
    const float* b2    = (const float*)d_in[8];
    float*       out   = (float*)d_out;

    int E = in_sizes[0] / 32;
    int ntiles = (E + TILE - 1) / TILE;
    int grid = (ntiles + TPC - 1) / TPC;

    cudaFuncSetAttribute(edge_mlp_lm,
                         cudaFuncAttributeMaxDynamicSharedMemorySize, SM_BYTES);
    edge_mlp_lm<<<grid, THREADS, SM_BYTES>>>(src, dst, ea, u, batch,
                                             W1, b1, W2, b2, out, E, ntiles);
}

// round 9
// speedup vs baseline: 1.0336x; 1.0336x over previous
#include <cuda_runtime.h>
#include <cuda_fp16.h>
#include <cstdint>

#define THREADS 384      // 12 independent warps, 1 CTA/SM
#define XS_H 120         // halves; 240B row; 15 units ≡ 7 mod 8 -> ldmatrix conflict-free
#define W1_H 120

// smem: xs 12*32*120*2 = 92160, w1 64*120*2 = 15360, b1 256, b2 128
#define SM_BYTES (92160 + 15360 + 256 + 128)

__device__ __forceinline__ uint2 f4_to_h4(float4 v) {
    __half2 lo = __floats2half2_rn(v.x, v.y);
    __half2 hi = __floats2half2_rn(v.z, v.w);
    uint2 r; r.x = *(uint32_t*)&lo; r.y = *(uint32_t*)&hi; return r;
}
__device__ __forceinline__ uint32_t f2_to_h2(float x, float y) {
    __half2 h = __floats2half2_rn(x, y);
    return *(uint32_t*)&h;
}
__device__ __forceinline__ uint32_t s2u(const void* p) {
    uint32_t a;
    asm("{ .reg .u64 t; cvta.to.shared.u64 t, %1; cvt.u32.u64 %0, t; }" : "=r"(a) : "l"(p));
    return a;
}
__device__ __forceinline__ void ldm_x4(uint32_t* r, uint32_t addr) {
    asm volatile("ldmatrix.sync.aligned.m8n8.x4.shared.b16 {%0,%1,%2,%3}, [%4];"
        : "=r"(r[0]), "=r"(r[1]), "=r"(r[2]), "=r"(r[3]) : "r"(addr));
}
__device__ __forceinline__ void mma_f16(float* d, const uint32_t* a, const uint32_t* b) {
    asm volatile(
        "mma.sync.aligned.m16n8k16.row.col.f32.f16.f16.f32 "
        "{%0,%1,%2,%3}, {%4,%5,%6,%7}, {%8,%9}, {%0,%1,%2,%3};"
        : "+f"(d[0]), "+f"(d[1]), "+f"(d[2]), "+f"(d[3])
        : "r"(a[0]), "r"(a[1]), "r"(a[2]), "r"(a[3]), "r"(b[0]), "r"(b[1]));
}

extern "C" __global__ void __launch_bounds__(THREADS, 1)
edge_mlp_ind(const float* __restrict__ src, const float* __restrict__ dst,
             const float* __restrict__ ea, const float* __restrict__ u,
             const int* __restrict__ batch,
             const float* __restrict__ W1, const float* __restrict__ b1,
             const float* __restrict__ W2, const float* __restrict__ b2,
             float* __restrict__ out, int E, int nchunks)
{
    extern __shared__ char smraw[];
    __half* xs  = (__half*)smraw;                 // [12 warps][32 rows][XS_H]
    __half* w1s = xs + 12 * 32 * XS_H;            // [64 n][W1_H k]
    float*  b1s = (float*)(w1s + 64 * W1_H);      // 64
    float*  b2s = b1s + 64;                       // 32

    const int t    = threadIdx.x;
    const int w    = t >> 5;
    const int lane = t & 31;
    const int gid  = lane >> 2;   // 0..7
    const int ctid = lane & 3;    // 0..3

    // ---- stage W1 [n][k] halves + biases (once per CTA) ----
    {
        const float2* w12 = (const float2*)W1;     // 64*56 float2
        for (int i = t; i < 3584; i += THREADS) {
            int n = i / 56, k2 = i % 56;
            float2 v = w12[i];
            *(uint32_t*)&w1s[n * W1_H + 2 * k2] = f2_to_h2(v.x, v.y);
        }
        if (t < 64) b1s[t] = b1[t];
        if (t >= 64 && t < 96) b2s[t - 64] = b2[t - 64];
    }

    // ---- W2 fragments persist in registers: full 32 outputs per warp ----
    uint32_t w2r[4][4][2];   // [ks][nt][b0/b1]
    #pragma unroll
    for (int ks = 0; ks < 4; ks++)
        #pragma unroll
        for (int nt = 0; nt < 4; nt++) {
            int n  = 8 * nt + gid;
            int k0 = 16 * ks + 2 * ctid;
            float2 v0 = *(const float2*)&W2[n * 64 + k0];
            float2 v1 = *(const float2*)&W2[n * 64 + k0 + 8];
            w2r[ks][nt][0] = f2_to_h2(v0.x, v0.y);
            w2r[ks][nt][1] = f2_to_h2(v1.x, v1.y);
        }
    __syncthreads();   // w1s/b visible to all warps

    __half* xw = xs + w * 32 * XS_H;      // this warp's private 32-row tile
    const uint32_t xw_u = s2u(xw);
    const uint32_t w1_u = s2u(w1s);

    // ldmatrix per-lane offsets
    const int rp   = ((lane >> 3) & 1) * 8 + (lane & 7);
    const int kp   = (lane >> 4) * 16;                    // bytes
    const int aoff = rp * (XS_H * 2) + kp;
    const int np   = ((lane >> 4) & 1) * 8 + (lane & 7);
    const int bkp  = ((lane >> 3) & 1) * 16;
    const int boff = np * (W1_H * 2) + bkp;

    const float4* src4 = (const float4*)src;
    const float4* dst4 = (const float4*)dst;
    const float4* ea4  = (const float4*)ea;
    const float4* u4   = (const float4*)u;

    const int r4 = lane >> 3, c8 = lane & 7;   // staging: 4 rows x 8 cols
    const int r8 = lane >> 2, c4 = lane & 3;   // u: 8 rows x 4 cols

    // ---- per-warp independent chunk loop: 32 edges per chunk ----
    for (int ch = blockIdx.x * 12 + w; ch < nchunks; ch += gridDim.x * 12) {
        const int e0 = ch * 32;

        __syncwarp();   // prior chunk's xs reads done before overwrite
        // ---- stage own 32 rows, coalesced 4-row windows ----
        #pragma unroll
        for (int blk = 0; blk < 3; blk++) {
            const float4* a4 = (blk == 0) ? src4 : (blk == 1) ? dst4 : ea4;
            #pragma unroll
            for (int it = 0; it < 8; it++) {
                int r = r4 + 4 * it;
                int e = e0 + r;
                float4 v = make_float4(0.f, 0.f, 0.f, 0.f);
                if (e < E) v = a4[(size_t)e * 8 + c8];
                *(uint2*)&xw[r * XS_H + blk * 32 + c8 * 4] = f4_to_h4(v);
            }
        }
        #pragma unroll
        for (int it = 0; it < 4; it++) {
            int r = r8 + 8 * it;
            int e = e0 + r;
            float4 v = make_float4(0.f, 0.f, 0.f, 0.f);
            if (e < E) { int bi = batch[e]; v = u4[(size_t)bi * 4 + c4]; }
            *(uint2*)&xw[r * XS_H + 96 + c4 * 4] = f4_to_h4(v);
        }
        __syncwarp();

        // ===== GEMM1: [32x112] @ [112x64], full N per warp =====
        float acc[2][8][4];
        #pragma unroll
        for (int mt = 0; mt < 2; mt++)
            #pragma unroll
            for (int nt = 0; nt < 8; nt++)
                #pragma unroll
                for (int q = 0; q < 4; q++) acc[mt][nt][q] = 0.f;

        #pragma unroll
        for (int ks = 0; ks < 7; ks++) {
            uint32_t a[2][4], b[4][4];
            #pragma unroll
            for (int mt = 0; mt < 2; mt++)
                ldm_x4(a[mt], xw_u + 16 * mt * (XS_H * 2) + aoff + ks * 32);
            #pragma unroll
            for (int ntp = 0; ntp < 4; ntp++)
                ldm_x4(b[ntp], w1_u + 16 * ntp * (W1_H * 2) + boff + ks * 32);
            #pragma unroll
            for (int mt = 0; mt < 2; mt++)
                #pragma unroll
                for (int ntp = 0; ntp < 4; ntp++) {
                    mma_f16(acc[mt][2 * ntp],     a[mt], &b[ntp][0]);
                    mma_f16(acc[mt][2 * ntp + 1], a[mt], &b[ntp][2]);
                }
        }

        // ===== fused epilogue1 + GEMM2, all in registers =====
        float acc2[2][4][4];
        #pragma unroll
        for (int mt = 0; mt < 2; mt++)
            #pragma unroll
            for (int nt = 0; nt < 4; nt++)
                #pragma unroll
                for (int q = 0; q < 4; q++) acc2[mt][nt][q] = 0.f;

        #pragma unroll
        for (int ks = 0; ks < 4; ks++) {
            // h cols 16ks + {2ctid, 2ctid+1} and +8; biases from smem
            float2 bA = *(const float2*)&b1s[16 * ks + 2 * ctid];
            float2 bB = *(const float2*)&b1s[16 * ks + 8 + 2 * ctid];
            uint32_t a2[2][4];
            #pragma unroll
            for (int mt = 0; mt < 2; mt++) {
                a2[mt][0] = f2_to_h2(fmaxf(acc[mt][2*ks][0] + bA.x, 0.f),
                                     fmaxf(acc[mt][2*ks][1] + bA.y, 0.f));
                a2[mt][1] = f2_to_h2(fmaxf(acc[mt][2*ks][2] + bA.x, 0.f),
                                     fmaxf(acc[mt][2*ks][3] + bA.y, 0.f));
                a2[mt][2] = f2_to_h2(fmaxf(acc[mt][2*ks+1][0] + bB.x, 0.f),
                                     fmaxf(acc[mt][2*ks+1][1] + bB.y, 0.f));
                a2[mt][3] = f2_to_h2(fmaxf(acc[mt][2*ks+1][2] + bB.x, 0.f),
                                     fmaxf(acc[mt][2*ks+1][3] + bB.y, 0.f));
            }
            #pragma unroll
            for (int nt = 0; nt < 4; nt++) {
                mma_f16(acc2[0][nt], a2[0], w2r[ks][nt]);
                mma_f16(acc2[1][nt], a2[1], w2r[ks][nt]);
            }
        }

        // ---- epilogue 2: bias + store ----
        #pragma unroll
        for (int mt = 0; mt < 2; mt++) {
            int e = e0 + 16 * mt + gid;
            #pragma unroll
            for (int nt = 0; nt < 4; nt++) {
                int c = 8 * nt + 2 * ctid;
                float2 bv = *(const float2*)&b2s[c];
                if (e < E) {
                    float2 v;
                    v.x = acc2[mt][nt][0] + bv.x;
                    v.y = acc2[mt][nt][1] + bv.y;
                    *(float2*)&out[(size_t)e * 32 + c] = v;
                }
                if (e + 8 < E) {
                    float2 v;
                    v.x = acc2[mt][nt][2] + bv.x;
                    v.y = acc2[mt][nt][3] + bv.y;
                    *(float2*)&out[(size_t)(e + 8) * 32 + c] = v;
                }
            }
        }
    }
}

extern "C" void kernel_launch(void* const* d_in, const int* in_sizes, int n_in,
                              void* d_out, int out_size) {
    const float* src   = (const float*)d_in[0];
    const float* dst   = (const float*)d_in[1];
    const float* ea    = (const float*)d_in[2];
    const float* u     = (const float*)d_in[3];
    const int*   batch = (const int*)d_in[4];
    const float* W1    = (const float*)d_in[5];
    const float* b1    = (const float*)d_in[6];
    const float* W2    = (const float*)d_in[7];
    const float* b2    = (const float*)d_in[8];
    float*       out   = (float*)d_out;

    int E = in_sizes[0] / 32;
    int nchunks = (E + 31) / 32;

    int nsm = 148;
    cudaDeviceGetAttribute(&nsm, cudaDevAttrMultiProcessorCount, 0);
    int grid = 4 * nsm;                       // ~4 waves of 1 CTA/SM; amortizes W1 staging
    int maxg = (nchunks + 11) / 12;
    if (grid > maxg) grid = maxg;

    cudaFuncSetAttribute(edge_mlp_ind,
                         cudaFuncAttributeMaxDynamicSharedMemorySize, SM_BYTES);
    edge_mlp_ind<<<grid, THREADS, SM_BYTES>>>(src, dst, ea, u, batch,
                                              W1, b1, W2, b2, out, E, nchunks);
}

// round 10
// speedup vs baseline: 1.2314x; 1.1915x over previous
#include <cuda_runtime.h>
#include <cuda_fp16.h>
#include <cstdint>

#define THREADS 384      // 12 independent warps, 1 CTA/SM
#define ROWS    16       // edges per warp-chunk
#define FS      100      // fp32 stage row stride (floats); 400B ≡ 16 mod 128 -> min-wf frag LDS
#define W1_H    120      // W1 fp16 stride (halves)

// smem: stage 12w * 2buf * 16 * 100 * 4 = 153600; W1 15360; b1 256; b2 128
#define STG_BYTES 153600
#define SM_BYTES  (STG_BYTES + 15360 + 256 + 128)

__device__ __forceinline__ uint32_t f2_to_h2(float x, float y) {
    __half2 h = __floats2half2_rn(x, y);
    return *(uint32_t*)&h;
}
__device__ __forceinline__ uint32_t s2u(const void* p) {
    uint32_t a;
    asm("{ .reg .u64 t; cvta.to.shared.u64 t, %1; cvt.u32.u64 %0, t; }" : "=r"(a) : "l"(p));
    return a;
}
__device__ __forceinline__ void cp16(uint32_t dst, const void* src, int sz) {
    asm volatile("cp.async.cg.shared.global [%0], [%1], 16, %2;"
                 :: "r"(dst), "l"(src), "r"(sz) : "memory");
}
__device__ __forceinline__ void ldm_x4(uint32_t* r, uint32_t addr) {
    asm volatile("ldmatrix.sync.aligned.m8n8.x4.shared.b16 {%0,%1,%2,%3}, [%4];"
        : "=r"(r[0]), "=r"(r[1]), "=r"(r[2]), "=r"(r[3]) : "r"(addr));
}
__device__ __forceinline__ void mma_f16(float* d, const uint32_t* a, const uint32_t* b) {
    asm volatile(
        "mma.sync.aligned.m16n8k16.row.col.f32.f16.f16.f32 "
        "{%0,%1,%2,%3}, {%4,%5,%6,%7}, {%8,%9}, {%0,%1,%2,%3};"
        : "+f"(d[0]), "+f"(d[1]), "+f"(d[2]), "+f"(d[3])
        : "r"(a[0]), "r"(a[1]), "r"(a[2]), "r"(a[3]), "r"(b[0]), "r"(b[1]));
}

extern "C" __global__ void __launch_bounds__(THREADS, 1)
edge_mlp_cp(const float* __restrict__ src, const float* __restrict__ dst,
            const float* __restrict__ ea, const float* __restrict__ u,
            const int* __restrict__ batch,
            const float* __restrict__ W1, const float* __restrict__ b1,
            const float* __restrict__ W2, const float* __restrict__ b2,
            float* __restrict__ out, int E, int nchunks)
{
    extern __shared__ char smraw[];
    float*  stg = (float*)smraw;                      // [12][2][16][FS]
    __half* w1s = (__half*)(smraw + STG_BYTES);       // [64 n][W1_H k]
    float*  b1s = (float*)(smraw + STG_BYTES + 15360);
    float*  b2s = b1s + 64;

    const int t    = threadIdx.x;
    const int w    = t >> 5;
    const int lane = t & 31;
    const int gid  = lane >> 2;   // 0..7
    const int ctid = lane & 3;    // 0..3

    // ---- stage W1 [n][k] halves + biases (once per CTA) ----
    {
        const float2* w12 = (const float2*)W1;   // 64*56 float2
        for (int i = t; i < 3584; i += THREADS) {
            int n = i / 56, k2 = i % 56;
            float2 v = w12[i];
            *(uint32_t*)&w1s[n * W1_H + 2 * k2] = f2_to_h2(v.x, v.y);
        }
        if (t < 64) b1s[t] = b1[t];
        if (t >= 64 && t < 96) b2s[t - 64] = b2[t - 64];
    }

    // ---- W2 fragments persist in registers (full 32 outputs per warp) ----
    uint32_t w2r[4][4][2];
    #pragma unroll
    for (int ks = 0; ks < 4; ks++)
        #pragma unroll
        for (int nt = 0; nt < 4; nt++) {
            int n  = 8 * nt + gid;
            int k0 = 16 * ks + 2 * ctid;
            float2 v0 = *(const float2*)&W2[n * 64 + k0];
            float2 v1 = *(const float2*)&W2[n * 64 + k0 + 8];
            w2r[ks][nt][0] = f2_to_h2(v0.x, v0.y);
            w2r[ks][nt][1] = f2_to_h2(v1.x, v1.y);
        }
    __syncthreads();

    float* buf0 = stg + w * (2 * ROWS * FS);
    float* buf1 = buf0 + ROWS * FS;
    const uint32_t buf0_u = s2u(buf0);
    const uint32_t buf1_u = s2u(buf1);
    const uint32_t w1_u   = s2u(w1s);

    // W1 ldmatrix per-lane offset: matrices (n0-7,k0),(n0-7,k8),(n8-15,k0),(n8-15,k8)
    const int np   = ((lane >> 4) & 1) * 8 + (lane & 7);
    const int bkp  = ((lane >> 3) & 1) * 16;
    const int boff = np * (W1_H * 2) + bkp;

    // cp.async staging of src|dst|ea: 16 rows x 24 16B-segs = 384 segs, 12/lane
    auto stage = [&](uint32_t bufu, int ch) {
        const int e0 = ch * ROWS;
        #pragma unroll
        for (int i = 0; i < 12; i++) {
            int s = lane + 32 * i;
            int r = s / 24, c = s % 24;
            int e = e0 + r;
            int ec = e < E ? e : E - 1;
            const float4* a4 = (c < 8) ? (const float4*)src
                             : (c < 16) ? (const float4*)dst
                                        : (const float4*)ea;
            const void* sp = (const void*)(a4 + (size_t)ec * 8 + (c & 7));
            cp16(bufu + (uint32_t)(r * (FS * 4) + c * 16), sp, e < E ? 16 : 0);
        }
        asm volatile("cp.async.commit_group;" ::: "memory");
    };

    int ch = blockIdx.x * 12 + w;
    const int step = gridDim.x * 12;

    int bA = 0, bB = 0;
    if (ch < nchunks) {
        stage(buf0_u, ch);
        int eA = ch * ROWS + gid, eB = eA + 8;
        bA = batch[eA < E ? eA : E - 1];
        bB = batch[eB < E ? eB : E - 1];
    }

    int pb = 0;
    for (; ch < nchunks; ch += step) {
        const int e0 = ch * ROWS;
        const int nch = ch + step;
        int nA = bA, nB = bB;
        if (nch < nchunks) {
            stage(pb ? buf0_u : buf1_u, nch);
            int eA = nch * ROWS + gid, eB = eA + 8;
            nA = batch[eA < E ? eA : E - 1];
            nB = batch[eB < E ? eB : E - 1];
            asm volatile("cp.async.wait_group 1;" ::: "memory");
        } else {
            asm volatile("cp.async.wait_group 0;" ::: "memory");
        }
        __syncwarp();

        const float* bp = pb ? buf1 : buf0;

        // u[batch] fragments for ks=6 (k 96..111), straight from gmem (L2-resident)
        uint32_t au[4];
        {
            float2 a0 = *(const float2*)&u[(size_t)bA * 16 + 2 * ctid];
            float2 a1 = *(const float2*)&u[(size_t)bB * 16 + 2 * ctid];
            float2 a2 = *(const float2*)&u[(size_t)bA * 16 + 8 + 2 * ctid];
            float2 a3 = *(const float2*)&u[(size_t)bB * 16 + 8 + 2 * ctid];
            au[0] = f2_to_h2(a0.x, a0.y);
            au[1] = f2_to_h2(a1.x, a1.y);
            au[2] = f2_to_h2(a2.x, a2.y);
            au[3] = f2_to_h2(a3.x, a3.y);
        }

        // ===== GEMM1: [16x112] @ [112x64] =====
        float acc[8][4];
        #pragma unroll
        for (int nt = 0; nt < 8; nt++)
            #pragma unroll
            for (int q = 0; q < 4; q++) acc[nt][q] = 0.f;

        #pragma unroll
        for (int ks = 0; ks < 7; ks++) {
            uint32_t a[4];
            if (ks < 6) {
                int k0 = 16 * ks + 2 * ctid;
                float2 f0 = *(const float2*)&bp[gid * FS + k0];
                float2 f1 = *(const float2*)&bp[(gid + 8) * FS + k0];
                float2 f2 = *(const float2*)&bp[gid * FS + k0 + 8];
                float2 f3 = *(const float2*)&bp[(gid + 8) * FS + k0 + 8];
                a[0] = f2_to_h2(f0.x, f0.y);
                a[1] = f2_to_h2(f1.x, f1.y);
                a[2] = f2_to_h2(f2.x, f2.y);
                a[3] = f2_to_h2(f3.x, f3.y);
            } else {
                a[0] = au[0]; a[1] = au[1]; a[2] = au[2]; a[3] = au[3];
            }
            #pragma unroll
            for (int ntp = 0; ntp < 4; ntp++) {
                uint32_t b[4];
                ldm_x4(b, w1_u + 16 * ntp * (W1_H * 2) + boff + ks * 32);
                mma_f16(acc[2 * ntp],     a, &b[0]);
                mma_f16(acc[2 * ntp + 1], a, &b[2]);
            }
        }

        // ===== fused epilogue1 + GEMM2 (all registers) =====
        float acc2[4][4];
        #pragma unroll
        for (int nt = 0; nt < 4; nt++)
            #pragma unroll
            for (int q = 0; q < 4; q++) acc2[nt][q] = 0.f;

        #pragma unroll
        for (int ks = 0; ks < 4; ks++) {
            float2 bAv = *(const float2*)&b1s[16 * ks + 2 * ctid];
            float2 bBv = *(const float2*)&b1s[16 * ks + 8 + 2 * ctid];
            uint32_t a2[4];
            a2[0] = f2_to_h2(fmaxf(acc[2*ks][0] + bAv.x, 0.f),
                             fmaxf(acc[2*ks][1] + bAv.y, 0.f));
            a2[1] = f2_to_h2(fmaxf(acc[2*ks][2] + bAv.x, 0.f),
                             fmaxf(acc[2*ks][3] + bAv.y, 0.f));
            a2[2] = f2_to_h2(fmaxf(acc[2*ks+1][0] + bBv.x, 0.f),
                             fmaxf(acc[2*ks+1][1] + bBv.y, 0.f));
            a2[3] = f2_to_h2(fmaxf(acc[2*ks+1][2] + bBv.x, 0.f),
                             fmaxf(acc[2*ks+1][3] + bBv.y, 0.f));
            #pragma unroll
            for (int nt = 0; nt < 4; nt++)
                mma_f16(acc2[nt], a2, w2r[ks][nt]);
        }

        // ---- epilogue 2: bias + store ----
        {
            int eA2 = e0 + gid, eB2 = e0 + 8 + gid;
            #pragma unroll
            for (int nt = 0; nt < 4; nt++) {
                int c = 8 * nt + 2 * ctid;
                float2 bv = *(const float2*)&b2s[c];
                if (eA2 < E) {
                    float2 v;
                    v.x = acc2[nt][0] + bv.x;
                    v.y = acc2[nt][1] + bv.y;
                    *(float2*)&out[(size_t)eA2 * 32 + c] = v;
                }
                if (eB2 < E) {
                    float2 v;
                    v.x = acc2[nt][2] + bv.x;
                    v.y = acc2[nt][3] + bv.y;
                    *(float2*)&out[(size_t)eB2 * 32 + c] = v;
                }
            }
        }

        bA = nA; bB = nB;
        pb ^= 1;
    }
}

extern "C" void kernel_launch(void* const* d_in, const int* in_sizes, int n_in,
                              void* d_out, int out_size) {
    const float* src   = (const float*)d_in[0];
    const float* dst   = (const float*)d_in[1];
    const float* ea    = (const float*)d_in[2];
    const float* u     = (const float*)d_in[3];
    const int*   batch = (const int*)d_in[4];
    const float* W1    = (const float*)d_in[5];
    const float* b1    = (const float*)d_in[6];
    const float* W2    = (const float*)d_in[7];
    const float* b2    = (const float*)d_in[8];
    float*       out   = (float*)d_out;

    int E = in_sizes[0] / 32;
    int nchunks = (E + ROWS - 1) / ROWS;

    int nsm = 148;
    cudaDeviceGetAttribute(&nsm, cudaDevAttrMultiProcessorCount, 0);
    int grid = 4 * nsm;
    int maxg = (nchunks + 11) / 12;
    if (grid > maxg) grid = maxg;

    cudaFuncSetAttribute(edge_mlp_cp,
                         cudaFuncAttributeMaxDynamicSharedMemorySize, SM_BYTES);
    edge_mlp_cp<<<grid, THREADS, SM_BYTES>>>(src, dst, ea, u, batch,
                                             W1, b1, W2, b2, out, E, nchunks);
}